// round 11
// baseline (speedup 1.0000x reference)
#include <cuda_runtime.h>

#define N_NODES 100000
#define N_EDGES 1600000
#define IN_CH 128
#define HID 128
#define OUT_CH 64
#define MAXDEG 64

// ---------------- scratch (static device globals; no allocation) ----------------
__device__ int   g_cnt[N_NODES];
__device__ int   g_ell[N_NODES * MAXDEG];     // ELL adjacency (by dst)
__device__ int2  g_ell2[N_NODES * MAXDEG];    // (src, bits(dinv[src])) packed
__device__ float g_dinv[N_NODES];
__device__ float g_xs1[N_NODES * HID];        // x @ W1 (unscaled)
__device__ float g_h  [N_NODES * HID];        // layer-1 activations
__device__ float g_xs2[N_NODES * OUT_CH];     // (h @ W2) * dinv[row]

// ---------------- f32x2 packed-FMA helpers ----------------
__device__ __forceinline__ unsigned long long ffma2(unsigned long long a,
                                                    unsigned long long b,
                                                    unsigned long long c) {
    unsigned long long d;
    asm("fma.rn.f32x2 %0, %1, %2, %3;" : "=l"(d) : "l"(a), "l"(b), "l"(c));
    return d;
}
__device__ __forceinline__ unsigned long long pack2(float x) {
    unsigned long long d;
    asm("mov.b64 %0, {%1, %1};" : "=l"(d) : "f"(x));
    return d;
}
__device__ __forceinline__ float2 unpack2(unsigned long long v) {
    float2 r;
    asm("mov.b64 {%0, %1}, %2;" : "=f"(r.x), "=f"(r.y) : "l"(v));
    return r;
}

// ---------------- prep: ELL build ----------------
__global__ void k_zero_cnt() {
    int i = blockIdx.x * blockDim.x + threadIdx.x;
    if (i < N_NODES) g_cnt[i] = 0;
}

__global__ void k_scatter_ell(const int* __restrict__ ei) {
    int e = blockIdx.x * blockDim.x + threadIdx.x;
    if (e < N_EDGES) {
        int src = ei[e];
        int dst = ei[N_EDGES + e];
        int slot = atomicAdd(&g_cnt[dst], 1);
        g_ell[dst * MAXDEG + slot] = src;
    }
}

__global__ void k_dinv() {
    int i = blockIdx.x * blockDim.x + threadIdx.x;
    if (i < N_NODES) g_dinv[i] = rsqrtf((float)(g_cnt[i] + 1));  // +1 self loop
}

// pack (src, dinv[src]) per slot; coalesced ell read + write, scattered dinv gather
__global__ void k_coef() {
    int idx = blockIdx.x * blockDim.x + threadIdx.x;   // over N_NODES*MAXDEG
    int v = idx >> 6;
    int s = idx & (MAXDEG - 1);
    if (v < N_NODES && s < g_cnt[v]) {
        int src = g_ell[idx];
        g_ell2[idx] = make_int2(src, __float_as_int(g_dinv[src]));
    }
}

// ---------------- GEMM: out = (in @ W) * (scale ? dinv : 1) ----------------
// BM=64, TM=4 (small register tile -> 4 blocks/SM, 32 warps for latency hiding)
template <int NOUT, bool SCALE>
__device__ __forceinline__ void gemm_body(const float* __restrict__ in,
                                          const float* __restrict__ W,
                                          float* __restrict__ out) {
    constexpr int BM = 64, BK = 32, TM = 4, TN = NOUT / 16, TP = TN / 2;
    __shared__ __align__(16) float xt[BK][BM + 4];   // transposed x tile
    __shared__ __align__(16) float ws[BK][NOUT];

    int tid = threadIdx.x;
    int tcol = tid & 15;
    int trow = tid >> 4;
    int brow = blockIdx.x * BM;

    unsigned long long acc[TM][TP];
#pragma unroll
    for (int i = 0; i < TM; i++)
#pragma unroll
        for (int j = 0; j < TP; j++) acc[i][j] = 0ull;

    for (int k0 = 0; k0 < 128; k0 += BK) {
        // x tile: 64 rows x 32 k, stored transposed (2 float4 per thread)
#pragma unroll
        for (int it = 0; it < BM * BK / (4 * 256); it++) {
            int idx = tid + it * 256;
            int r = idx >> 3;      // row 0..63
            int kq = idx & 7;      // k-quad 0..7
            int row = brow + r;
            float4 v = make_float4(0.f, 0.f, 0.f, 0.f);
            if (row < N_NODES)
                v = *(const float4*)(in + row * 128 + k0 + kq * 4);
            xt[kq * 4 + 0][r] = v.x;
            xt[kq * 4 + 1][r] = v.y;
            xt[kq * 4 + 2][r] = v.z;
            xt[kq * 4 + 3][r] = v.w;
        }
        // W tile: 32 x NOUT
#pragma unroll
        for (int it = 0; it < BK * NOUT / (4 * 256); it++) {
            int idx = tid + it * 256;
            int r = idx / (NOUT / 4);
            int cq = idx % (NOUT / 4);
            *(float4*)(&ws[r][cq * 4]) = *(const float4*)(W + (k0 + r) * NOUT + cq * 4);
        }
        __syncthreads();

#pragma unroll 4
        for (int kk = 0; kk < BK; kk++) {
            float4 a0 = *(const float4*)(&xt[kk][trow * TM]);
            unsigned long long pa[TM];
            pa[0] = pack2(a0.x); pa[1] = pack2(a0.y);
            pa[2] = pack2(a0.z); pa[3] = pack2(a0.w);

            unsigned long long b[TP];
#pragma unroll
            for (int j = 0; j < TP; j += 2) {
                ulonglong2 bv = *(const ulonglong2*)(&ws[kk][tcol * TN + j * 2]);
                b[j] = bv.x;
                b[j + 1] = bv.y;
            }
#pragma unroll
            for (int i = 0; i < TM; i++)
#pragma unroll
                for (int j = 0; j < TP; j++) acc[i][j] = ffma2(pa[i], b[j], acc[i][j]);
        }
        __syncthreads();
    }

#pragma unroll
    for (int i = 0; i < TM; i++) {
        int row = brow + trow * TM + i;
        if (row < N_NODES) {
            float di = SCALE ? g_dinv[row] : 1.0f;
            float r[TN];
#pragma unroll
            for (int j = 0; j < TP; j++) {
                float2 u = unpack2(acc[i][j]);
                r[j * 2] = u.x * di;
                r[j * 2 + 1] = u.y * di;
            }
#pragma unroll
            for (int j = 0; j < TN; j += 4)
                *(float4*)(out + row * NOUT + tcol * TN + j) =
                    make_float4(r[j], r[j + 1], r[j + 2], r[j + 3]);
        }
    }
}

__global__ void __launch_bounds__(256) k_gemm1(const float* __restrict__ x,
                                               const float* __restrict__ W1) {
    gemm_body<HID, false>(x, W1, g_xs1);
}
__global__ void __launch_bounds__(256) k_gemm2(const float* __restrict__ W2) {
    gemm_body<OUT_CH, true>(g_h, W2, g_xs2);
}

// ---------------- aggregation layer 1: warp per node, 128 feats ----------------
// h[v] = l2norm(relu(dinv[v]*(sum dinv[src]*xs1[src] + dinv[v]*xs1[v]) + b1))
__global__ void __launch_bounds__(256) k_agg1(const float* __restrict__ b1) {
    int gw = (blockIdx.x * blockDim.x + threadIdx.x) >> 5;
    int lane = threadIdx.x & 31;
    if (gw >= N_NODES) return;
    int v = gw;

    const float4* xrow = (const float4*)g_xs1;
    float dvv = g_dinv[v];
    float4 self = xrow[v * 32 + lane];
    float4 acc;
    acc.x = self.x * dvv; acc.y = self.y * dvv;
    acc.z = self.z * dvv; acc.w = self.w * dvv;

    int deg = g_cnt[v];
    int base = v * MAXDEG;
    for (int e = 0; e < deg; e += 32) {
        int m = deg - e;
        int c = 0;
        float dv = 0.f;
        if (lane < m) {
            int2 p = g_ell2[base + e + lane];   // one coalesced 8B load
            c = p.x;
            dv = __int_as_float(p.y);
        }
        if (m >= 32) {
#pragma unroll
            for (int j = 0; j < 32; j++) {
                int col = __shfl_sync(0xffffffffu, c, j);
                float d = __shfl_sync(0xffffffffu, dv, j);
                float4 val = xrow[col * 32 + lane];
                acc.x = fmaf(val.x, d, acc.x);
                acc.y = fmaf(val.y, d, acc.y);
                acc.z = fmaf(val.z, d, acc.z);
                acc.w = fmaf(val.w, d, acc.w);
            }
        } else {
            for (int j = 0; j < m; j++) {
                int col = __shfl_sync(0xffffffffu, c, j);
                float d = __shfl_sync(0xffffffffu, dv, j);
                float4 val = xrow[col * 32 + lane];
                acc.x = fmaf(val.x, d, acc.x);
                acc.y = fmaf(val.y, d, acc.y);
                acc.z = fmaf(val.z, d, acc.z);
                acc.w = fmaf(val.w, d, acc.w);
            }
        }
    }

    float4 bb = ((const float4*)b1)[lane];
    float4 h;
    h.x = fmaxf(fmaf(dvv, acc.x, bb.x), 0.f);
    h.y = fmaxf(fmaf(dvv, acc.y, bb.y), 0.f);
    h.z = fmaxf(fmaf(dvv, acc.z, bb.z), 0.f);
    h.w = fmaxf(fmaf(dvv, acc.w, bb.w), 0.f);

    float ss = h.x * h.x + h.y * h.y + h.z * h.z + h.w * h.w;
#pragma unroll
    for (int off = 16; off; off >>= 1) ss += __shfl_xor_sync(0xffffffffu, ss, off);
    float sc = 1.0f / fmaxf(sqrtf(ss), 1e-12f);
    h.x *= sc; h.y *= sc; h.z *= sc; h.w *= sc;

    ((float4*)g_h)[v * 32 + lane] = h;
}

// ---------------- aggregation layer 2: warp per node, 64 feats ----------------
// out[v] = dinv[v]*(sum xs2[src] + xs2[v]) + b2   (dinv[src] folded in gemm2)
__global__ void __launch_bounds__(256) k_agg2(const float* __restrict__ b2,
                                              float* __restrict__ out) {
    int gw = (blockIdx.x * blockDim.x + threadIdx.x) >> 5;
    int lane = threadIdx.x & 31;
    if (gw >= N_NODES) return;
    int v = gw;

    const float2* xrow = (const float2*)g_xs2;
    float2 acc = xrow[v * 32 + lane];  // self term

    int deg = g_cnt[v];
    int base = v * MAXDEG;
    for (int e = 0; e < deg; e += 32) {
        int m = deg - e;
        int c = (lane < m) ? g_ell[base + e + lane] : 0;
        if (m >= 32) {
#pragma unroll
            for (int j = 0; j < 32; j++) {
                int col = __shfl_sync(0xffffffffu, c, j);
                float2 val = xrow[col * 32 + lane];
                acc.x += val.x; acc.y += val.y;
            }
        } else {
            for (int j = 0; j < m; j++) {
                int col = __shfl_sync(0xffffffffu, c, j);
                float2 val = xrow[col * 32 + lane];
                acc.x += val.x; acc.y += val.y;
            }
        }
    }

    float di = g_dinv[v];
    float2 bb = ((const float2*)b2)[lane];
    float2 o;
    o.x = fmaf(di, acc.x, bb.x);
    o.y = fmaf(di, acc.y, bb.y);
    ((float2*)out)[v * 32 + lane] = o;
}

// ---------------- launch (prep chain forked onto a side stream) ----------------
static cudaStream_t s_side = nullptr;
static cudaEvent_t e_fork = nullptr, e_join = nullptr;

extern "C" void kernel_launch(void* const* d_in, const int* in_sizes, int n_in,
                              void* d_out, int out_size) {
    const float* x  = (const float*)d_in[0];
    const int*   ei = (const int*)d_in[1];   // JAX default: int64 request -> int32
    const float* W1 = (const float*)d_in[2];
    const float* b1 = (const float*)d_in[3];
    const float* W2 = (const float*)d_in[4];
    const float* b2 = (const float*)d_in[5];
    float* out = (float*)d_out;

    if (!s_side) {  // first call is the uncaptured correctness run
        cudaStreamCreateWithFlags(&s_side, cudaStreamNonBlocking);
        cudaEventCreateWithFlags(&e_fork, cudaEventDisableTiming);
        cudaEventCreateWithFlags(&e_join, cudaEventDisableTiming);
    }

    // fork: ELL prep on side stream (hidden under gemm1), gemm1 on main stream
    cudaEventRecord(e_fork, 0);
    cudaStreamWaitEvent(s_side, e_fork, 0);

    k_zero_cnt<<<(N_NODES + 255) / 256, 256, 0, s_side>>>();
    k_scatter_ell<<<(N_EDGES + 255) / 256, 256, 0, s_side>>>(ei);
    k_dinv<<<(N_NODES + 255) / 256, 256, 0, s_side>>>();
    k_coef<<<(N_NODES * MAXDEG + 255) / 256, 256, 0, s_side>>>();
    cudaEventRecord(e_join, s_side);

    k_gemm1<<<(N_NODES + 63) / 64, 256>>>(x, W1);

    // join: everything below needs both gemm1 and the ELL/dinv/coef
    cudaStreamWaitEvent(0, e_join, 0);

    k_agg1<<<(N_NODES * 32 + 255) / 256, 256>>>(b1);
    k_gemm2<<<(N_NODES + 63) / 64, 256>>>(W2);
    k_agg2<<<(N_NODES * 32 + 255) / 256, 256>>>(b2, out);
}